// round 3
// baseline (speedup 1.0000x reference)
#include <cuda_runtime.h>
#include <cuda_bf16.h>
#include <cstdint>

// ---------------------------------------------------------------------------
// Problem constants
// ---------------------------------------------------------------------------
#define BB 64
#define SS 8192
#define DD 128
#define UU 128
#define FF 16
#define CLIP_C 10.0f
#define BIG_NUMBER 1e9f
#define TS 128              // s-rows per CTA tile

// Scratch (device globals; no allocation allowed)
__device__ float          g_qb[BB * UU];        // q@W1 + b1 + b2
__device__ __nv_bfloat16  g_W2T_hi[UU * DD];    // W2^T hi split, [u][d]
__device__ __nv_bfloat16  g_W2T_lo[UU * DD];    // W2^T lo split, [u][d]

// ---------------------------------------------------------------------------
// Helpers (baseline PTX only: ldmatrix + mma.sync, both compute_80+)
// ---------------------------------------------------------------------------
__device__ __forceinline__ uint32_t smem_u32(const void* p) {
    uint32_t a;
    asm("{ .reg .u64 t; cvta.to.shared.u64 t, %1; cvt.u32.u64 %0, t; }"
        : "=r"(a) : "l"(p));
    return a;
}

#define LDMX4(r0, r1, r2, r3, addr) \
    asm volatile("ldmatrix.sync.aligned.m8n8.x4.shared.b16 {%0,%1,%2,%3}, [%4];" \
                 : "=r"(r0), "=r"(r1), "=r"(r2), "=r"(r3) : "r"(addr))

#define MMA16816(c0, c1, c2, c3, a0, a1, a2, a3, b0, b1) \
    asm volatile("mma.sync.aligned.m16n8k16.row.col.f32.bf16.bf16.f32 " \
                 "{%0,%1,%2,%3}, {%4,%5,%6,%7}, {%8,%9}, {%0,%1,%2,%3};" \
                 : "+f"(c0), "+f"(c1), "+f"(c2), "+f"(c3) \
                 : "r"(a0), "r"(a1), "r"(a2), "r"(a3), "r"(b0), "r"(b1))

// ---------------------------------------------------------------------------
// Prep: qb (blocks 0..63) + W2^T bf16 hi/lo split (blocks 64..79)
// ---------------------------------------------------------------------------
__global__ void prep_kernel(const float* __restrict__ dec,
                            const float* __restrict__ W1w,
                            const float* __restrict__ W1b,
                            const float* __restrict__ W2b,
                            const float* __restrict__ W2w) {
    int blk = blockIdx.x;
    if (blk < BB) {
        int b = blk, u = threadIdx.x;
        __shared__ float dsh[DD];
        dsh[u] = dec[b * DD + u];
        __syncthreads();
        float acc = 0.f;
#pragma unroll 8
        for (int d = 0; d < DD; d++) acc += dsh[d] * W1w[d * UU + u];
        g_qb[b * UU + u] = acc + W1b[u] + W2b[u];
    } else {
        int j = blk - BB;           // 0..15, each handles 8 u rows
        int d = threadIdx.x;        // 128 threads
#pragma unroll
        for (int k = 0; k < 8; k++) {
            int u = j * 8 + k;
            float x = W2w[d * UU + u];
            __nv_bfloat16 h = __float2bfloat16(x);
            float lo = x - __bfloat162float(h);
            g_W2T_hi[u * DD + d] = h;
            g_W2T_lo[u * DD + d] = __float2bfloat16(lo);
        }
    }
}

// ---------------------------------------------------------------------------
// Main kernel: per-CTA 128x128 tile, K = enc @ W2 via 3-term bf16-split
// mma.sync (fp32 accum in registers), fused tanh/V-dot/clip/mask epilogue.
//
// SMEM: bf16 tiles padded to 136 elems (272 B) per row -> conflict-free
// ldmatrix (272 mod 128 = 16B shift per row; 8 rows cover 8 distinct chunks).
// ---------------------------------------------------------------------------
#define ROWB 272u           // padded row stride in bytes (136 bf16)
#define SM_A_HI 0u
#define SM_A_LO (SM_A_HI + 128u * ROWB)      // 34816
#define SM_W_HI (SM_A_LO + 128u * ROWB)      // 69632
#define SM_W_LO (SM_W_HI + 128u * ROWB)      // 104448
#define SM_AUX  (SM_W_LO + 128u * ROWB)      // 139264
#define SM_Q    (SM_AUX)                      // 128 f32
#define SM_V    (SM_AUX + 512u)               // 128 f32
#define SM_PART (SM_AUX + 1024u)              // 128*2 f32
#define SM_TOTAL (SM_AUX + 2048u)

extern __shared__ unsigned char smx[];

__global__ void __launch_bounds__(256, 1)
main_kernel(const float* __restrict__ enc_out,
            const float* __restrict__ mask,
            const float* __restrict__ Vw,
            const float* __restrict__ Vb,
            float* __restrict__ logits) {
    const int b   = blockIdx.y;
    const int s0  = blockIdx.x * TS;
    const int tid = threadIdx.x;
    const int wid = tid >> 5;
    const int lid = tid & 31;
    const int warp_m = wid & 3;    // 4 warp-rows of 32 s
    const int warp_n = wid >> 2;   // 2 warp-cols of 64 u
    const uint32_t sb = smem_u32(smx);

    float* sh_q    = (float*)(smx + SM_Q);
    float* sh_v    = (float*)(smx + SM_V);
    float* sh_part = (float*)(smx + SM_PART);

    if (tid < UU) { sh_q[tid] = g_qb[b * UU + tid]; sh_v[tid] = Vw[tid]; }

    // ---- fill A (enc fp32 -> bf16 hi/lo, padded rows) ----
    {
        const int row  = tid >> 1;
        const int half = tid & 1;
        const float* src = enc_out + ((size_t)b * SS + s0 + row) * DD + half * 64;
        unsigned char* dhi = smx + SM_A_HI + row * ROWB + half * 128;
        unsigned char* dlo = smx + SM_A_LO + row * ROWB + half * 128;
#pragma unroll
        for (int i = 0; i < 16; i++) {
            float4 x = ((const float4*)src)[i];
            __nv_bfloat16 h0 = __float2bfloat16(x.x), h1 = __float2bfloat16(x.y);
            __nv_bfloat16 h2 = __float2bfloat16(x.z), h3 = __float2bfloat16(x.w);
            __nv_bfloat162 hp0 = __halves2bfloat162(h0, h1);
            __nv_bfloat162 hp1 = __halves2bfloat162(h2, h3);
            __nv_bfloat162 lp0 = __halves2bfloat162(
                __float2bfloat16(x.x - __bfloat162float(h0)),
                __float2bfloat16(x.y - __bfloat162float(h1)));
            __nv_bfloat162 lp1 = __halves2bfloat162(
                __float2bfloat16(x.z - __bfloat162float(h2)),
                __float2bfloat16(x.w - __bfloat162float(h3)));
            ((uint2*)(dhi))[i] = make_uint2(*(uint32_t*)&hp0, *(uint32_t*)&hp1);
            ((uint2*)(dlo))[i] = make_uint2(*(uint32_t*)&lp0, *(uint32_t*)&lp1);
        }
    }

    // ---- fill W (prepped bf16 [u][d] -> padded rows) ----
    {
        const int row  = tid >> 1;
        const int half = tid & 1;
        const uint4* shi = (const uint4*)((const char*)g_W2T_hi + row * 256 + half * 128);
        const uint4* slo = (const uint4*)((const char*)g_W2T_lo + row * 256 + half * 128);
        uint4* dhi = (uint4*)(smx + SM_W_HI + row * ROWB + half * 128);
        uint4* dlo = (uint4*)(smx + SM_W_LO + row * ROWB + half * 128);
#pragma unroll
        for (int i = 0; i < 8; i++) { dhi[i] = shi[i]; dlo[i] = slo[i]; }
    }
    __syncthreads();

    // ---- per-lane ldmatrix base offsets (within a buffer) ----
    // A (16x16 tile): row = l&15, colByte = (l>>4)*16
    const uint32_t a_off = (uint32_t)(lid & 15) * ROWB + (uint32_t)((lid >> 4) & 1) * 16u
                           + (uint32_t)(warp_m * 32) * ROWB;
    // B (two n8k16 tiles per x4): n_row = (l&7) + ((l&16)?8:0), colByte = (l&8)?16:0
    const uint32_t b_off = ((uint32_t)(lid & 7) + (uint32_t)((lid >> 4) & 1) * 8u) * ROWB
                           + (uint32_t)((lid >> 3) & 1) * 16u
                           + (uint32_t)(warp_n * 64) * ROWB;

    float acc[2][8][4];
#pragma unroll
    for (int mi = 0; mi < 2; mi++)
#pragma unroll
        for (int ni = 0; ni < 8; ni++)
#pragma unroll
            for (int j = 0; j < 4; j++) acc[mi][ni][j] = 0.f;

    // ---- 3 split terms: Ahi*Whi + Ahi*Wlo + Alo*Whi ----
#pragma unroll 1
    for (int t = 0; t < 3; t++) {
        const uint32_t abase = sb + (t == 2 ? SM_A_LO : SM_A_HI) + a_off;
        const uint32_t wbase = sb + (t == 1 ? SM_W_LO : SM_W_HI) + b_off;
#pragma unroll 1
        for (int kk = 0; kk < 8; kk++) {
            const uint32_t kb = (uint32_t)kk * 32u;
            uint32_t a[2][4];
            LDMX4(a[0][0], a[0][1], a[0][2], a[0][3], abase + kb);
            LDMX4(a[1][0], a[1][1], a[1][2], a[1][3], abase + 16u * ROWB + kb);
            uint32_t bf[8][2];
#pragma unroll
            for (int np = 0; np < 4; np++) {
                LDMX4(bf[2 * np][0], bf[2 * np][1], bf[2 * np + 1][0], bf[2 * np + 1][1],
                      wbase + (uint32_t)(np * 16) * ROWB + kb);
            }
#pragma unroll
            for (int mi = 0; mi < 2; mi++)
#pragma unroll
                for (int ni = 0; ni < 8; ni++)
                    MMA16816(acc[mi][ni][0], acc[mi][ni][1], acc[mi][ni][2], acc[mi][ni][3],
                             a[mi][0], a[mi][1], a[mi][2], a[mi][3],
                             bf[ni][0], bf[ni][1]);
        }
    }

    // ---- epilogue: sum_u V[u]*tanh(q[u]+K[s][u]) ----
    const int gid = lid >> 2;   // row within 8
    const int tig = lid & 3;    // col-pair selector
#pragma unroll
    for (int mi = 0; mi < 2; mi++) {
        float sumA = 0.f, sumB = 0.f;
#pragma unroll
        for (int ni = 0; ni < 8; ni++) {
            int cb = warp_n * 64 + ni * 8 + 2 * tig;
            float v0 = sh_v[cb], v1 = sh_v[cb + 1];
            float q0 = sh_q[cb], q1 = sh_q[cb + 1];
            sumA += v0 * tanhf(q0 + acc[mi][ni][0]) + v1 * tanhf(q1 + acc[mi][ni][1]);
            sumB += v0 * tanhf(q0 + acc[mi][ni][2]) + v1 * tanhf(q1 + acc[mi][ni][3]);
        }
        sumA += __shfl_xor_sync(0xffffffff, sumA, 1);
        sumA += __shfl_xor_sync(0xffffffff, sumA, 2);
        sumB += __shfl_xor_sync(0xffffffff, sumB, 1);
        sumB += __shfl_xor_sync(0xffffffff, sumB, 2);
        if (tig == 0) {
            int rowA = warp_m * 32 + mi * 16 + gid;
            sh_part[rowA * 2 + warp_n] = sumA;
            sh_part[(rowA + 8) * 2 + warp_n] = sumB;
        }
    }
    __syncthreads();

    if (tid < TS) {
        float sc = sh_part[tid * 2] + sh_part[tid * 2 + 1] + Vb[0];
        float lg = CLIP_C * tanhf(sc)
                 - mask[(size_t)b * SS + s0 + tid] * BIG_NUMBER;
        logits[(size_t)b * SS + s0 + tid] = lg;
    }
}

// ---------------------------------------------------------------------------
// Softmax + first-occurrence argmax + gather (per batch)
// ---------------------------------------------------------------------------
#define SM_THREADS 512

__global__ void softmax_kernel(const float* __restrict__ logits,
                               const float* __restrict__ enc_input,
                               float* __restrict__ probs,
                               float* __restrict__ out_index,
                               float* __restrict__ gathered) {
    const int b = blockIdx.x;
    const int tid = threadIdx.x;
    const float* L = logits + (size_t)b * SS;
    float* P = probs + (size_t)b * SS;

    __shared__ float smax[SM_THREADS];
    __shared__ int   sidx[SM_THREADS];
    __shared__ float ssum[SM_THREADS];

    float bm = -3.0e38f; int bi = 0;
    for (int s = tid; s < SS; s += SM_THREADS) {
        float v = L[s];
        if (v > bm) { bm = v; bi = s; }
    }
    smax[tid] = bm; sidx[tid] = bi;
    __syncthreads();
    for (int off = SM_THREADS / 2; off > 0; off >>= 1) {
        if (tid < off) {
            float ov = smax[tid + off]; int oi = sidx[tid + off];
            if (ov > smax[tid] || (ov == smax[tid] && oi < sidx[tid])) {
                smax[tid] = ov; sidx[tid] = oi;
            }
        }
        __syncthreads();
    }
    const float M = smax[0];
    const int idx = sidx[0];

    float ls = 0.f;
    for (int s = tid; s < SS; s += SM_THREADS) ls += expf(L[s] - M);
    ssum[tid] = ls;
    __syncthreads();
    for (int off = SM_THREADS / 2; off > 0; off >>= 1) {
        if (tid < off) ssum[tid] += ssum[tid + off];
        __syncthreads();
    }
    const float invZ = 1.0f / ssum[0];

    for (int s = tid; s < SS; s += SM_THREADS) P[s] = expf(L[s] - M) * invZ;

    if (tid == 0) out_index[b] = (float)idx;
    if (tid < FF)
        gathered[b * FF + tid] = enc_input[((size_t)b * SS + idx) * FF + tid];
}

// ---------------------------------------------------------------------------
// launch
// ---------------------------------------------------------------------------
extern "C" void kernel_launch(void* const* d_in, const int* in_sizes, int n_in,
                              void* d_out, int out_size) {
    const float* dec     = (const float*)d_in[0];
    const float* enc_in  = (const float*)d_in[1];
    const float* enc_out = (const float*)d_in[2];
    const float* mask    = (const float*)d_in[3];
    const float* W1w     = (const float*)d_in[4];
    const float* W1b     = (const float*)d_in[5];
    const float* W2w     = (const float*)d_in[6];
    const float* W2b     = (const float*)d_in[7];
    const float* Vw      = (const float*)d_in[8];
    const float* Vb      = (const float*)d_in[9];

    float* out    = (float*)d_out;
    float* logits = out;
    float* probs  = out + (size_t)BB * SS;
    float* oidx   = out + (size_t)2 * BB * SS;
    float* gath   = oidx + BB;

    cudaFuncSetAttribute(main_kernel,
                         cudaFuncAttributeMaxDynamicSharedMemorySize, SM_TOTAL);

    prep_kernel<<<BB + 16, 128>>>(dec, W1w, W1b, W2b, W2w);
    main_kernel<<<dim3(SS / TS, BB), 256, SM_TOTAL>>>(
        enc_out, mask, Vw, Vb, logits);
    softmax_kernel<<<BB, SM_THREADS>>>(logits, enc_in, probs, oidx, gath);
}

// round 8
// speedup vs baseline: 1.5584x; 1.5584x over previous
#include <cuda_runtime.h>
#include <cuda_bf16.h>
#include <cstdint>

// ---------------------------------------------------------------------------
// Problem constants
// ---------------------------------------------------------------------------
#define BB 64
#define SS 8192
#define DD 128
#define UU 128
#define FF 16
#define CLIP_C 10.0f
#define BIG_NUMBER 1e9f
#define TS 128              // s-rows per CTA tile (R3-proven config)

// Scratch (device globals; no allocation allowed)
__device__ float          g_qb[BB * UU];        // q@W1 + b1 + b2
__device__ __nv_bfloat16  g_W2T_hi[UU * DD];    // W2^T hi split, [u][d]
__device__ __nv_bfloat16  g_W2T_lo[UU * DD];    // W2^T lo split, [u][d]

// ---------------------------------------------------------------------------
// Helpers (baseline PTX only: ldmatrix + mma.sync + approx MUFU)
// ---------------------------------------------------------------------------
__device__ __forceinline__ uint32_t smem_u32(const void* p) {
    uint32_t a;
    asm("{ .reg .u64 t; cvta.to.shared.u64 t, %1; cvt.u32.u64 %0, t; }"
        : "=r"(a) : "l"(p));
    return a;
}

#define LDMX4(r0, r1, r2, r3, addr) \
    asm volatile("ldmatrix.sync.aligned.m8n8.x4.shared.b16 {%0,%1,%2,%3}, [%4];" \
                 : "=r"(r0), "=r"(r1), "=r"(r2), "=r"(r3) : "r"(addr))

#define MMA16816(c0, c1, c2, c3, a0, a1, a2, a3, b0, b1) \
    asm volatile("mma.sync.aligned.m16n8k16.row.col.f32.bf16.bf16.f32 " \
                 "{%0,%1,%2,%3}, {%4,%5,%6,%7}, {%8,%9}, {%0,%1,%2,%3};" \
                 : "+f"(c0), "+f"(c1), "+f"(c2), "+f"(c3) \
                 : "r"(a0), "r"(a1), "r"(a2), "r"(a3), "r"(b0), "r"(b1))

// tanh(x) = 1 - 2/(exp(2x)+1), via ex2.approx + rcp.approx (~1e-6 abs err,
// monotonic -> ordering/argmax safe)
__device__ __forceinline__ float fast_tanh(float x) {
    float e, r;
    asm("ex2.approx.f32 %0, %1;" : "=f"(e) : "f"(x * 2.885390081777927f));
    asm("rcp.approx.f32 %0, %1;" : "=f"(r) : "f"(e + 1.0f));
    return fmaf(-2.0f, r, 1.0f);
}

__device__ __forceinline__ float fast_exp(float x) {
    float e;
    asm("ex2.approx.f32 %0, %1;" : "=f"(e) : "f"(x * 1.4426950408889634f));
    return e;
}

// ---------------------------------------------------------------------------
// Prep: qb (blocks 0..63) + W2^T bf16 hi/lo split (blocks 64..79)
// ---------------------------------------------------------------------------
__global__ void prep_kernel(const float* __restrict__ dec,
                            const float* __restrict__ W1w,
                            const float* __restrict__ W1b,
                            const float* __restrict__ W2b,
                            const float* __restrict__ W2w) {
    int blk = blockIdx.x;
    if (blk < BB) {
        int b = blk, u = threadIdx.x;
        __shared__ float dsh[DD];
        dsh[u] = dec[b * DD + u];
        __syncthreads();
        float acc = 0.f;
#pragma unroll 8
        for (int d = 0; d < DD; d++) acc += dsh[d] * W1w[d * UU + u];
        g_qb[b * UU + u] = acc + W1b[u] + W2b[u];
    } else {
        int j = blk - BB;           // 0..15 -> d rows j*8..j*8+7
        int u = threadIdx.x;        // 128 threads, coalesced W2w reads
#pragma unroll
        for (int k = 0; k < 8; k++) {
            int d = j * 8 + k;
            float x = W2w[d * UU + u];
            __nv_bfloat16 h = __float2bfloat16(x);
            float lo = x - __bfloat162float(h);
            g_W2T_hi[u * DD + d] = h;
            g_W2T_lo[u * DD + d] = __float2bfloat16(lo);
        }
    }
}

// ---------------------------------------------------------------------------
// Main kernel (R3-proven layout): per-CTA 128x128 tile, K = enc @ W2 via
// 3-term bf16-split mma.sync, fused FAST-tanh / V-dot / clip / mask epilogue.
// ---------------------------------------------------------------------------
#define ROWB 272u           // padded row stride in bytes (136 bf16)
#define SM_A_HI 0u
#define SM_A_LO (SM_A_HI + 128u * ROWB)      // 34816
#define SM_W_HI (SM_A_LO + 128u * ROWB)      // 69632
#define SM_W_LO (SM_W_HI + 128u * ROWB)      // 104448
#define SM_AUX  (SM_W_LO + 128u * ROWB)      // 139264
#define SM_Q    (SM_AUX)                      // 128 f32
#define SM_V    (SM_AUX + 512u)               // 128 f32
#define SM_PART (SM_AUX + 1024u)              // 128*2 f32
#define SM_TOTAL (SM_AUX + 2048u)

extern __shared__ unsigned char smx[];

__global__ void __launch_bounds__(256, 1)
main_kernel(const float* __restrict__ enc_out,
            const float* __restrict__ mask,
            const float* __restrict__ Vw,
            const float* __restrict__ Vb,
            float* __restrict__ logits) {
    const int b   = blockIdx.y;
    const int s0  = blockIdx.x * TS;
    const int tid = threadIdx.x;
    const int wid = tid >> 5;
    const int lid = tid & 31;
    const int warp_m = wid & 3;    // 4 warp-rows of 32 s
    const int warp_n = wid >> 2;   // 2 warp-cols of 64 u
    const uint32_t sb = smem_u32(smx);

    float* sh_q    = (float*)(smx + SM_Q);
    float* sh_v    = (float*)(smx + SM_V);
    float* sh_part = (float*)(smx + SM_PART);

    if (tid < UU) { sh_q[tid] = g_qb[b * UU + tid]; sh_v[tid] = Vw[tid]; }

    // ---- fill A (enc fp32 -> bf16 hi/lo, padded rows) ----
    {
        const int row  = tid >> 1;
        const int half = tid & 1;
        const float* src = enc_out + ((size_t)b * SS + s0 + row) * DD + half * 64;
        unsigned char* dhi = smx + SM_A_HI + row * ROWB + half * 128;
        unsigned char* dlo = smx + SM_A_LO + row * ROWB + half * 128;
#pragma unroll
        for (int i = 0; i < 16; i++) {
            float4 x = ((const float4*)src)[i];
            __nv_bfloat16 h0 = __float2bfloat16(x.x), h1 = __float2bfloat16(x.y);
            __nv_bfloat16 h2 = __float2bfloat16(x.z), h3 = __float2bfloat16(x.w);
            __nv_bfloat162 hp0 = __halves2bfloat162(h0, h1);
            __nv_bfloat162 hp1 = __halves2bfloat162(h2, h3);
            __nv_bfloat162 lp0 = __halves2bfloat162(
                __float2bfloat16(x.x - __bfloat162float(h0)),
                __float2bfloat16(x.y - __bfloat162float(h1)));
            __nv_bfloat162 lp1 = __halves2bfloat162(
                __float2bfloat16(x.z - __bfloat162float(h2)),
                __float2bfloat16(x.w - __bfloat162float(h3)));
            ((uint2*)(dhi))[i] = make_uint2(*(uint32_t*)&hp0, *(uint32_t*)&hp1);
            ((uint2*)(dlo))[i] = make_uint2(*(uint32_t*)&lp0, *(uint32_t*)&lp1);
        }
    }

    // ---- fill W (prepped bf16 [u][d] -> padded rows) ----
    {
        const int row  = tid >> 1;
        const int half = tid & 1;
        const uint4* shi = (const uint4*)((const char*)g_W2T_hi + row * 256 + half * 128);
        const uint4* slo = (const uint4*)((const char*)g_W2T_lo + row * 256 + half * 128);
        uint4* dhi = (uint4*)(smx + SM_W_HI + row * ROWB + half * 128);
        uint4* dlo = (uint4*)(smx + SM_W_LO + row * ROWB + half * 128);
#pragma unroll
        for (int i = 0; i < 8; i++) { dhi[i] = shi[i]; dlo[i] = slo[i]; }
    }
    __syncthreads();

    // ---- per-lane ldmatrix base offsets ----
    const uint32_t a_off = (uint32_t)(lid & 15) * ROWB + (uint32_t)((lid >> 4) & 1) * 16u
                           + (uint32_t)(warp_m * 32) * ROWB;
    const uint32_t b_off = ((uint32_t)(lid & 7) + (uint32_t)((lid >> 4) & 1) * 8u) * ROWB
                           + (uint32_t)((lid >> 3) & 1) * 16u
                           + (uint32_t)(warp_n * 64) * ROWB;

    float acc[2][8][4];
#pragma unroll
    for (int mi = 0; mi < 2; mi++)
#pragma unroll
        for (int ni = 0; ni < 8; ni++)
#pragma unroll
            for (int j = 0; j < 4; j++) acc[mi][ni][j] = 0.f;

    // ---- 3 split terms: Ahi*Whi + Ahi*Wlo + Alo*Whi ----
#pragma unroll 1
    for (int t = 0; t < 3; t++) {
        const uint32_t abase = sb + (t == 2 ? SM_A_LO : SM_A_HI) + a_off;
        const uint32_t wbase = sb + (t == 1 ? SM_W_LO : SM_W_HI) + b_off;
#pragma unroll 1
        for (int kk = 0; kk < 8; kk++) {
            const uint32_t kb = (uint32_t)kk * 32u;
            uint32_t a[2][4];
            LDMX4(a[0][0], a[0][1], a[0][2], a[0][3], abase + kb);
            LDMX4(a[1][0], a[1][1], a[1][2], a[1][3], abase + 16u * ROWB + kb);
            uint32_t bf[8][2];
#pragma unroll
            for (int np = 0; np < 4; np++) {
                LDMX4(bf[2 * np][0], bf[2 * np][1], bf[2 * np + 1][0], bf[2 * np + 1][1],
                      wbase + (uint32_t)(np * 16) * ROWB + kb);
            }
#pragma unroll
            for (int mi = 0; mi < 2; mi++)
#pragma unroll
                for (int ni = 0; ni < 8; ni++)
                    MMA16816(acc[mi][ni][0], acc[mi][ni][1], acc[mi][ni][2], acc[mi][ni][3],
                             a[mi][0], a[mi][1], a[mi][2], a[mi][3],
                             bf[ni][0], bf[ni][1]);
        }
    }

    // ---- epilogue: sum_u V[u]*tanh(q[u]+K[s][u]) with fast tanh ----
    const int gid = lid >> 2;   // row within 8
    const int tig = lid & 3;    // col-pair selector
#pragma unroll
    for (int mi = 0; mi < 2; mi++) {
        float sumA = 0.f, sumB = 0.f;
#pragma unroll
        for (int ni = 0; ni < 8; ni++) {
            int cb = warp_n * 64 + ni * 8 + 2 * tig;
            float v0 = sh_v[cb], v1 = sh_v[cb + 1];
            float q0 = sh_q[cb], q1 = sh_q[cb + 1];
            sumA += v0 * fast_tanh(q0 + acc[mi][ni][0]) + v1 * fast_tanh(q1 + acc[mi][ni][1]);
            sumB += v0 * fast_tanh(q0 + acc[mi][ni][2]) + v1 * fast_tanh(q1 + acc[mi][ni][3]);
        }
        sumA += __shfl_xor_sync(0xffffffff, sumA, 1);
        sumA += __shfl_xor_sync(0xffffffff, sumA, 2);
        sumB += __shfl_xor_sync(0xffffffff, sumB, 1);
        sumB += __shfl_xor_sync(0xffffffff, sumB, 2);
        if (tig == 0) {
            int rowA = warp_m * 32 + mi * 16 + gid;
            sh_part[rowA * 2 + warp_n] = sumA;
            sh_part[(rowA + 8) * 2 + warp_n] = sumB;
        }
    }
    __syncthreads();

    if (tid < TS) {
        float sc = sh_part[tid * 2] + sh_part[tid * 2 + 1] + Vb[0];
        float lg = CLIP_C * fast_tanh(sc)
                 - mask[(size_t)b * SS + s0 + tid] * BIG_NUMBER;
        logits[(size_t)b * SS + s0 + tid] = lg;
    }
}

// ---------------------------------------------------------------------------
// Softmax + first-occurrence argmax + gather (per batch), single-pass
// ---------------------------------------------------------------------------
#define SM_THREADS 512
#define PER_TH (SS / SM_THREADS)   // 16

__global__ void softmax_kernel(const float* __restrict__ logits,
                               const float* __restrict__ enc_input,
                               float* __restrict__ probs,
                               float* __restrict__ out_index,
                               float* __restrict__ gathered) {
    const int b = blockIdx.x;
    const int tid = threadIdx.x;
    const float* L = logits + (size_t)b * SS;
    float* P = probs + (size_t)b * SS;

    __shared__ float smax[SM_THREADS];
    __shared__ int   sidx[SM_THREADS];
    __shared__ float ssum[SM_THREADS];

    float vals[PER_TH];
    float bm = -3.0e38f; int bi = 0;
#pragma unroll
    for (int k = 0; k < PER_TH; k++) {
        int s = tid + k * SM_THREADS;
        float v = L[s];
        vals[k] = v;
        if (v > bm) { bm = v; bi = s; }
    }
    smax[tid] = bm; sidx[tid] = bi;
    __syncthreads();
    for (int off = SM_THREADS / 2; off > 0; off >>= 1) {
        if (tid < off) {
            float ov = smax[tid + off]; int oi = sidx[tid + off];
            if (ov > smax[tid] || (ov == smax[tid] && oi < sidx[tid])) {
                smax[tid] = ov; sidx[tid] = oi;
            }
        }
        __syncthreads();
    }
    const float M = smax[0];
    const int idx = sidx[0];

    float ls = 0.f;
#pragma unroll
    for (int k = 0; k < PER_TH; k++) {
        vals[k] = fast_exp(vals[k] - M);
        ls += vals[k];
    }
    ssum[tid] = ls;
    __syncthreads();
    for (int off = SM_THREADS / 2; off > 0; off >>= 1) {
        if (tid < off) ssum[tid] += ssum[tid + off];
        __syncthreads();
    }
    const float invZ = 1.0f / ssum[0];

#pragma unroll
    for (int k = 0; k < PER_TH; k++)
        P[tid + k * SM_THREADS] = vals[k] * invZ;

    if (tid == 0) out_index[b] = (float)idx;
    if (tid < FF)
        gathered[b * FF + tid] = enc_input[((size_t)b * SS + idx) * FF + tid];
}

// ---------------------------------------------------------------------------
// launch
// ---------------------------------------------------------------------------
extern "C" void kernel_launch(void* const* d_in, const int* in_sizes, int n_in,
                              void* d_out, int out_size) {
    const float* dec     = (const float*)d_in[0];
    const float* enc_in  = (const float*)d_in[1];
    const float* enc_out = (const float*)d_in[2];
    const float* mask    = (const float*)d_in[3];
    const float* W1w     = (const float*)d_in[4];
    const float* W1b     = (const float*)d_in[5];
    const float* W2w     = (const float*)d_in[6];
    const float* W2b     = (const float*)d_in[7];
    const float* Vw      = (const float*)d_in[8];
    const float* Vb      = (const float*)d_in[9];

    float* out    = (float*)d_out;
    float* logits = out;
    float* probs  = out + (size_t)BB * SS;
    float* oidx   = out + (size_t)2 * BB * SS;
    float* gath   = oidx + BB;

    cudaFuncSetAttribute(main_kernel,
                         cudaFuncAttributeMaxDynamicSharedMemorySize, SM_TOTAL);

    prep_kernel<<<BB + 16, 128>>>(dec, W1w, W1b, W2b, W2w);
    main_kernel<<<dim3(SS / TS, BB), 256, SM_TOTAL>>>(
        enc_out, mask, Vw, Vb, logits);
    softmax_kernel<<<BB, SM_THREADS>>>(logits, enc_in, probs, oidx, gath);
}

// round 9
// speedup vs baseline: 1.5690x; 1.0068x over previous
#include <cuda_runtime.h>
#include <cuda_bf16.h>
#include <cstdint>

// ---------------------------------------------------------------------------
// Problem constants
// ---------------------------------------------------------------------------
#define BB 64
#define SS 8192
#define DD 128
#define UU 128
#define FF 16
#define CLIP_C 10.0f
#define BIG_NUMBER 1e9f
#define TS 128              // s-rows per CTA tile

// Scratch (device globals; no allocation allowed)
__device__ float          g_qb[BB * UU];        // q@W1 + b1 + b2
__device__ __nv_bfloat16  g_W2T_hi[UU * DD];    // W2^T hi split, [u][d]
__device__ __nv_bfloat16  g_W2T_lo[UU * DD];    // W2^T lo split, [u][d]

// ---------------------------------------------------------------------------
// Helpers (baseline PTX only: ldmatrix + mma.sync + approx MUFU)
// ---------------------------------------------------------------------------
__device__ __forceinline__ uint32_t smem_u32(const void* p) {
    uint32_t a;
    asm("{ .reg .u64 t; cvta.to.shared.u64 t, %1; cvt.u32.u64 %0, t; }"
        : "=r"(a) : "l"(p));
    return a;
}

#define LDMX4(r0, r1, r2, r3, addr) \
    asm volatile("ldmatrix.sync.aligned.m8n8.x4.shared.b16 {%0,%1,%2,%3}, [%4];" \
                 : "=r"(r0), "=r"(r1), "=r"(r2), "=r"(r3) : "r"(addr))

#define MMA16816(c0, c1, c2, c3, a0, a1, a2, a3, b0, b1) \
    asm volatile("mma.sync.aligned.m16n8k16.row.col.f32.bf16.bf16.f32 " \
                 "{%0,%1,%2,%3}, {%4,%5,%6,%7}, {%8,%9}, {%0,%1,%2,%3};" \
                 : "+f"(c0), "+f"(c1), "+f"(c2), "+f"(c3) \
                 : "r"(a0), "r"(a1), "r"(a2), "r"(a3), "r"(b0), "r"(b1))

// tanh(x) = 1 - 2/(exp(2x)+1), via ex2.approx + rcp.approx (~1e-6 abs err,
// monotonic -> ordering/argmax safe)
__device__ __forceinline__ float fast_tanh(float x) {
    float e, r;
    asm("ex2.approx.f32 %0, %1;" : "=f"(e) : "f"(x * 2.885390081777927f));
    asm("rcp.approx.f32 %0, %1;" : "=f"(r) : "f"(e + 1.0f));
    return fmaf(-2.0f, r, 1.0f);
}

__device__ __forceinline__ float fast_exp(float x) {
    float e;
    asm("ex2.approx.f32 %0, %1;" : "=f"(e) : "f"(x * 1.4426950408889634f));
    return e;
}

// ---------------------------------------------------------------------------
// Prep: qb (blocks 0..63) + W2^T bf16 hi/lo split (blocks 64..79)
// ---------------------------------------------------------------------------
__global__ void prep_kernel(const float* __restrict__ dec,
                            const float* __restrict__ W1w,
                            const float* __restrict__ W1b,
                            const float* __restrict__ W2b,
                            const float* __restrict__ W2w) {
    int blk = blockIdx.x;
    if (blk < BB) {
        int b = blk, u = threadIdx.x;
        __shared__ float dsh[DD];
        dsh[u] = dec[b * DD + u];
        __syncthreads();
        float acc = 0.f;
#pragma unroll 8
        for (int d = 0; d < DD; d++) acc += dsh[d] * W1w[d * UU + u];
        g_qb[b * UU + u] = acc + W1b[u] + W2b[u];
    } else {
        int j = blk - BB;           // 0..15 -> d rows j*8..j*8+7
        int u = threadIdx.x;        // 128 threads, coalesced W2w reads
#pragma unroll
        for (int k = 0; k < 8; k++) {
            int d = j * 8 + k;
            float x = W2w[d * UU + u];
            __nv_bfloat16 h = __float2bfloat16(x);
            float lo = x - __bfloat162float(h);
            g_W2T_hi[u * DD + d] = h;
            g_W2T_lo[u * DD + d] = __float2bfloat16(lo);
        }
    }
}

// ---------------------------------------------------------------------------
// Main kernel: per-CTA 128x128 tile. K = enc @ W2 via 3-term bf16 split
// (Ahi*Whi + Ahi*Wlo + Alo*Whi) with FUSED kk-loop: fragments loaded once,
// all 48 MMAs issued back-to-back. Fast-tanh/V-dot/clip/mask epilogue.
// ---------------------------------------------------------------------------
#define ROWB 272u           // padded row stride in bytes (136 bf16)
#define SM_A_HI 0u
#define SM_A_LO (SM_A_HI + 128u * ROWB)      // 34816
#define SM_W_HI (SM_A_LO + 128u * ROWB)      // 69632
#define SM_W_LO (SM_W_HI + 128u * ROWB)      // 104448
#define SM_AUX  (SM_W_LO + 128u * ROWB)      // 139264
#define SM_Q    (SM_AUX)                      // 128 f32
#define SM_V    (SM_AUX + 512u)               // 128 f32
#define SM_PART (SM_AUX + 1024u)              // 128*2 f32
#define SM_TOTAL (SM_AUX + 2048u)

extern __shared__ unsigned char smx[];

__global__ void __launch_bounds__(256, 1)
main_kernel(const float* __restrict__ enc_out,
            const float* __restrict__ mask,
            const float* __restrict__ Vw,
            const float* __restrict__ Vb,
            float* __restrict__ logits) {
    const int b   = blockIdx.y;
    const int s0  = blockIdx.x * TS;
    const int tid = threadIdx.x;
    const int wid = tid >> 5;
    const int lid = tid & 31;
    const int warp_m = wid & 3;    // 4 warp-rows of 32 s
    const int warp_n = wid >> 2;   // 2 warp-cols of 64 u
    const uint32_t sb = smem_u32(smx);

    float* sh_q    = (float*)(smx + SM_Q);
    float* sh_v    = (float*)(smx + SM_V);
    float* sh_part = (float*)(smx + SM_PART);

    if (tid < UU) { sh_q[tid] = g_qb[b * UU + tid]; sh_v[tid] = Vw[tid]; }

    // ---- fill A (enc fp32 -> bf16 hi/lo, padded rows) ----
    {
        const int row  = tid >> 1;
        const int half = tid & 1;
        const float* src = enc_out + ((size_t)b * SS + s0 + row) * DD + half * 64;
        unsigned char* dhi = smx + SM_A_HI + row * ROWB + half * 128;
        unsigned char* dlo = smx + SM_A_LO + row * ROWB + half * 128;
#pragma unroll
        for (int i = 0; i < 16; i++) {
            float4 x = ((const float4*)src)[i];
            __nv_bfloat16 h0 = __float2bfloat16(x.x), h1 = __float2bfloat16(x.y);
            __nv_bfloat16 h2 = __float2bfloat16(x.z), h3 = __float2bfloat16(x.w);
            __nv_bfloat162 hp0 = __halves2bfloat162(h0, h1);
            __nv_bfloat162 hp1 = __halves2bfloat162(h2, h3);
            __nv_bfloat162 lp0 = __halves2bfloat162(
                __float2bfloat16(x.x - __bfloat162float(h0)),
                __float2bfloat16(x.y - __bfloat162float(h1)));
            __nv_bfloat162 lp1 = __halves2bfloat162(
                __float2bfloat16(x.z - __bfloat162float(h2)),
                __float2bfloat16(x.w - __bfloat162float(h3)));
            ((uint2*)(dhi))[i] = make_uint2(*(uint32_t*)&hp0, *(uint32_t*)&hp1);
            ((uint2*)(dlo))[i] = make_uint2(*(uint32_t*)&lp0, *(uint32_t*)&lp1);
        }
    }

    // ---- fill W (prepped bf16 [u][d] -> padded rows) ----
    {
        const int row  = tid >> 1;
        const int half = tid & 1;
        const uint4* shi = (const uint4*)((const char*)g_W2T_hi + row * 256 + half * 128);
        const uint4* slo = (const uint4*)((const char*)g_W2T_lo + row * 256 + half * 128);
        uint4* dhi = (uint4*)(smx + SM_W_HI + row * ROWB + half * 128);
        uint4* dlo = (uint4*)(smx + SM_W_LO + row * ROWB + half * 128);
#pragma unroll
        for (int i = 0; i < 8; i++) { dhi[i] = shi[i]; dlo[i] = slo[i]; }
    }
    __syncthreads();

    // ---- per-lane ldmatrix base offsets ----
    const uint32_t a_off = (uint32_t)(lid & 15) * ROWB + (uint32_t)((lid >> 4) & 1) * 16u
                           + (uint32_t)(warp_m * 32) * ROWB;
    const uint32_t b_off = ((uint32_t)(lid & 7) + (uint32_t)((lid >> 4) & 1) * 8u) * ROWB
                           + (uint32_t)((lid >> 3) & 1) * 16u
                           + (uint32_t)(warp_n * 64) * ROWB;

    const uint32_t a_hi_base = sb + SM_A_HI + a_off;
    const uint32_t a_lo_base = sb + SM_A_LO + a_off;
    const uint32_t w_hi_base = sb + SM_W_HI + b_off;
    const uint32_t w_lo_base = sb + SM_W_LO + b_off;

    float acc[2][8][4];
#pragma unroll
    for (int mi = 0; mi < 2; mi++)
#pragma unroll
        for (int ni = 0; ni < 8; ni++)
#pragma unroll
            for (int j = 0; j < 4; j++) acc[mi][ni][j] = 0.f;

    // ---- fused mainloop: load all fragments once per kk, 48 MMAs ----
#pragma unroll 1
    for (int kk = 0; kk < 8; kk++) {
        const uint32_t kb = (uint32_t)kk * 32u;

        uint32_t ahi[2][4], alo[2][4];
        LDMX4(ahi[0][0], ahi[0][1], ahi[0][2], ahi[0][3], a_hi_base + kb);
        LDMX4(ahi[1][0], ahi[1][1], ahi[1][2], ahi[1][3], a_hi_base + 16u * ROWB + kb);
        LDMX4(alo[0][0], alo[0][1], alo[0][2], alo[0][3], a_lo_base + kb);
        LDMX4(alo[1][0], alo[1][1], alo[1][2], alo[1][3], a_lo_base + 16u * ROWB + kb);

        uint32_t whi[8][2], wlo[8][2];
#pragma unroll
        for (int np = 0; np < 4; np++) {
            LDMX4(whi[2 * np][0], whi[2 * np][1], whi[2 * np + 1][0], whi[2 * np + 1][1],
                  w_hi_base + (uint32_t)(np * 16) * ROWB + kb);
            LDMX4(wlo[2 * np][0], wlo[2 * np][1], wlo[2 * np + 1][0], wlo[2 * np + 1][1],
                  w_lo_base + (uint32_t)(np * 16) * ROWB + kb);
        }

#pragma unroll
        for (int mi = 0; mi < 2; mi++) {
#pragma unroll
            for (int ni = 0; ni < 8; ni++) {
                MMA16816(acc[mi][ni][0], acc[mi][ni][1], acc[mi][ni][2], acc[mi][ni][3],
                         ahi[mi][0], ahi[mi][1], ahi[mi][2], ahi[mi][3],
                         whi[ni][0], whi[ni][1]);
                MMA16816(acc[mi][ni][0], acc[mi][ni][1], acc[mi][ni][2], acc[mi][ni][3],
                         ahi[mi][0], ahi[mi][1], ahi[mi][2], ahi[mi][3],
                         wlo[ni][0], wlo[ni][1]);
                MMA16816(acc[mi][ni][0], acc[mi][ni][1], acc[mi][ni][2], acc[mi][ni][3],
                         alo[mi][0], alo[mi][1], alo[mi][2], alo[mi][3],
                         whi[ni][0], whi[ni][1]);
            }
        }
    }

    // ---- epilogue: sum_u V[u]*tanh(q[u]+K[s][u]) with fast tanh ----
    const int gid = lid >> 2;   // row within 8
    const int tig = lid & 3;    // col-pair selector
#pragma unroll
    for (int mi = 0; mi < 2; mi++) {
        float sumA = 0.f, sumB = 0.f;
#pragma unroll
        for (int ni = 0; ni < 8; ni++) {
            int cb = warp_n * 64 + ni * 8 + 2 * tig;
            float v0 = sh_v[cb], v1 = sh_v[cb + 1];
            float q0 = sh_q[cb], q1 = sh_q[cb + 1];
            sumA += v0 * fast_tanh(q0 + acc[mi][ni][0]) + v1 * fast_tanh(q1 + acc[mi][ni][1]);
            sumB += v0 * fast_tanh(q0 + acc[mi][ni][2]) + v1 * fast_tanh(q1 + acc[mi][ni][3]);
        }
        sumA += __shfl_xor_sync(0xffffffff, sumA, 1);
        sumA += __shfl_xor_sync(0xffffffff, sumA, 2);
        sumB += __shfl_xor_sync(0xffffffff, sumB, 1);
        sumB += __shfl_xor_sync(0xffffffff, sumB, 2);
        if (tig == 0) {
            int rowA = warp_m * 32 + mi * 16 + gid;
            sh_part[rowA * 2 + warp_n] = sumA;
            sh_part[(rowA + 8) * 2 + warp_n] = sumB;
        }
    }
    __syncthreads();

    if (tid < TS) {
        float sc = sh_part[tid * 2] + sh_part[tid * 2 + 1] + Vb[0];
        float lg = CLIP_C * fast_tanh(sc)
                 - mask[(size_t)b * SS + s0 + tid] * BIG_NUMBER;
        logits[(size_t)b * SS + s0 + tid] = lg;
    }
}

// ---------------------------------------------------------------------------
// Softmax + first-occurrence argmax + gather (per batch), single-pass
// ---------------------------------------------------------------------------
#define SM_THREADS 512
#define PER_TH (SS / SM_THREADS)   // 16

__global__ void softmax_kernel(const float* __restrict__ logits,
                               const float* __restrict__ enc_input,
                               float* __restrict__ probs,
                               float* __restrict__ out_index,
                               float* __restrict__ gathered) {
    const int b = blockIdx.x;
    const int tid = threadIdx.x;
    const float* L = logits + (size_t)b * SS;
    float* P = probs + (size_t)b * SS;

    __shared__ float smax[SM_THREADS];
    __shared__ int   sidx[SM_THREADS];
    __shared__ float ssum[SM_THREADS];

    float vals[PER_TH];
    float bm = -3.0e38f; int bi = 0;
#pragma unroll
    for (int k = 0; k < PER_TH; k++) {
        int s = tid + k * SM_THREADS;
        float v = L[s];
        vals[k] = v;
        if (v > bm) { bm = v; bi = s; }
    }
    smax[tid] = bm; sidx[tid] = bi;
    __syncthreads();
    for (int off = SM_THREADS / 2; off > 0; off >>= 1) {
        if (tid < off) {
            float ov = smax[tid + off]; int oi = sidx[tid + off];
            if (ov > smax[tid] || (ov == smax[tid] && oi < sidx[tid])) {
                smax[tid] = ov; sidx[tid] = oi;
            }
        }
        __syncthreads();
    }
    const float M = smax[0];
    const int idx = sidx[0];

    float ls = 0.f;
#pragma unroll
    for (int k = 0; k < PER_TH; k++) {
        vals[k] = fast_exp(vals[k] - M);
        ls += vals[k];
    }
    ssum[tid] = ls;
    __syncthreads();
    for (int off = SM_THREADS / 2; off > 0; off >>= 1) {
        if (tid < off) ssum[tid] += ssum[tid + off];
        __syncthreads();
    }
    const float invZ = 1.0f / ssum[0];

#pragma unroll
    for (int k = 0; k < PER_TH; k++)
        P[tid + k * SM_THREADS] = vals[k] * invZ;

    if (tid == 0) out_index[b] = (float)idx;
    if (tid < FF)
        gathered[b * FF + tid] = enc_input[((size_t)b * SS + idx) * FF + tid];
}

// ---------------------------------------------------------------------------
// launch
// ---------------------------------------------------------------------------
extern "C" void kernel_launch(void* const* d_in, const int* in_sizes, int n_in,
                              void* d_out, int out_size) {
    const float* dec     = (const float*)d_in[0];
    const float* enc_in  = (const float*)d_in[1];
    const float* enc_out = (const float*)d_in[2];
    const float* mask    = (const float*)d_in[3];
    const float* W1w     = (const float*)d_in[4];
    const float* W1b     = (const float*)d_in[5];
    const float* W2w     = (const float*)d_in[6];
    const float* W2b     = (const float*)d_in[7];
    const float* Vw      = (const float*)d_in[8];
    const float* Vb      = (const float*)d_in[9];

    float* out    = (float*)d_out;
    float* logits = out;
    float* probs  = out + (size_t)BB * SS;
    float* oidx   = out + (size_t)2 * BB * SS;
    float* gath   = oidx + BB;

    cudaFuncSetAttribute(main_kernel,
                         cudaFuncAttributeMaxDynamicSharedMemorySize, SM_TOTAL);

    prep_kernel<<<BB + 16, 128>>>(dec, W1w, W1b, W2b, W2w);
    main_kernel<<<dim3(SS / TS, BB), 256, SM_TOTAL>>>(
        enc_out, mask, Vw, Vb, logits);
    softmax_kernel<<<BB, SM_THREADS>>>(logits, enc_in, probs, oidx, gath);
}